// round 7
// baseline (speedup 1.0000x reference)
#include <cuda_runtime.h>
#include <cstdint>

// ---------------------------------------------------------------------------
// CrossWarpingModule: B=2, C=64, H=W=256 -> 4 parity sub-images of 128x128,
// 8-head axial attention (per-head channel dim = 1), flow, bilinear warp.
//
//   K1  k_qkv  : 1x1 convs -> Q, K, V. Role-split: half the blocks compute Q
//                from cur (8 accumulators), half compute K+V from ref (16).
//                Low register pressure -> real occupancy.
//   K2  k_attn : MOMENT-BASED axial softmax (exp(qk) = sum q^n/n! k^n ->
//                29 per-line moments + deg-14 Horner per query), with
//                in-kernel transpose for the vertical direction.
//   K3  k_warp : bilinear border grid-sample; thread owns both x-parities of
//                an output pixel pair -> dense float2 stores (no sector waste).
// ---------------------------------------------------------------------------

#define PLANE 16384  // 128*128
typedef unsigned long long u64;
typedef unsigned int u32;

__device__ float g_Q [8][8][PLANE];
__device__ float g_K [8][8][PLANE];
__device__ float g_V [8][8][PLANE];
__device__ float g_flow[2][8][PLANE];  // dir0 = horizontal, dir1 = vertical

// ------------------------- packed f32x2 helpers ----------------------------
__device__ __forceinline__ u64 pk2f(float lo, float hi) {
    u64 r; asm("mov.b64 %0,{%1,%2};" : "=l"(r) : "f"(lo), "f"(hi)); return r;
}
__device__ __forceinline__ void upk2f(u64 v, float& lo, float& hi) {
    asm("mov.b64 {%0,%1},%2;" : "=f"(lo), "=f"(hi) : "l"(v));
}
__device__ __forceinline__ u64 fma2(u64 a, u64 b, u64 c) {
    u64 d; asm("fma.rn.f32x2 %0,%1,%2,%3;" : "=l"(d) : "l"(a), "l"(b), "l"(c)); return d;
}

// ---------------------------------------------------------------------------
// K1: QKV projections, role-split.
//   blocks [0,256)   role 0: Q  from cur  (8 u64 accumulators)
//   blocks [256,512) role 1: K,V from ref (16 u64 accumulators)
// Thread owns 2 consecutive original-x pixels packed in one f32x2 lane pair.
// ---------------------------------------------------------------------------
__global__ __launch_bounds__(256) void k_qkv(
    const float* __restrict__ cur, const float* __restrict__ ref,
    const float* __restrict__ Wq, const float* __restrict__ Wk,
    const float* __restrict__ Wv)
{
    __shared__ u64 sW[2][512];
    int t = threadIdx.x;
    int role = blockIdx.x >> 8;
    if (role == 0) {
        for (int i = t; i < 512; i += 256) {
            float w = Wq[i];
            sW[0][i] = pk2f(w, w);
        }
    } else {
        for (int i = t; i < 512; i += 256) {
            float wk = Wk[i], wv = Wv[i];
            sW[0][i] = pk2f(wk, wk);
            sW[1][i] = pk2f(wv, wv);
        }
    }
    __syncthreads();

    int idx = (blockIdx.x & 255) * 256 + t;  // 65536 = 2(b)*256(y)*128(xpair)
    int b   = idx >> 15;
    int rem = idx & 32767;
    int y   = rem >> 7;
    int xq  = rem & 127;
    int h2  = y >> 1, dyp = y & 1;

    // parity sub mapping: (dy,dx) -> s : (0,0)->0 (1,1)->1 (0,1)->2 (1,0)->3
    int s0  = dyp ? 3 : 0;               // even-x pixel (lo lane)
    int s1  = dyp ? 1 : 2;               // odd-x pixel (hi lane)
    int sb0 = s0 * 2 + b, sb1 = s1 * 2 + b;
    int off = h2 * 128 + xq;

    if (role == 0) {
        const float* srcp = cur + ((size_t)b * 64) * 65536 + y * 256 + xq * 2;
        u64 qa[8];
#pragma unroll
        for (int h = 0; h < 8; ++h) qa[h] = 0ull;
#pragma unroll 8
        for (int c = 0; c < 64; ++c) {
            float2 cv = *(const float2*)(srcp + (size_t)c * 65536);
            u64 c01 = pk2f(cv.x, cv.y);
#pragma unroll
            for (int h = 0; h < 8; ++h)
                qa[h] = fma2(sW[0][h * 64 + c], c01, qa[h]);
        }
#pragma unroll
        for (int h = 0; h < 8; ++h) {
            float lo, hi;
            upk2f(qa[h], lo, hi);
            g_Q[sb0][h][off] = lo; g_Q[sb1][h][off] = hi;
        }
    } else {
        const float* srcp = ref + ((size_t)b * 64) * 65536 + y * 256 + xq * 2;
        u64 ka[8], va[8];
#pragma unroll
        for (int h = 0; h < 8; ++h) { ka[h] = 0ull; va[h] = 0ull; }
#pragma unroll 4
        for (int c = 0; c < 64; ++c) {
            float2 rv = *(const float2*)(srcp + (size_t)c * 65536);
            u64 r01 = pk2f(rv.x, rv.y);
#pragma unroll
            for (int h = 0; h < 8; ++h) {
                ka[h] = fma2(sW[0][h * 64 + c], r01, ka[h]);
                va[h] = fma2(sW[1][h * 64 + c], r01, va[h]);
            }
        }
#pragma unroll
        for (int h = 0; h < 8; ++h) {
            float lo, hi;
            upk2f(ka[h], lo, hi);
            g_K[sb0][h][off] = lo; g_K[sb1][h][off] = hi;
            upk2f(va[h], lo, hi);
            g_V[sb0][h][off] = lo; g_V[sb1][h][off] = hi;
        }
    }
}

// ---------------------------------------------------------------------------
// K2: moment-based axial attention with in-kernel transpose for dir=1.
// Block = (dir, sb, 4 lines); 128 threads, warp per line.
// ---------------------------------------------------------------------------
#define NDEG 14

__global__ __launch_bounds__(128) void k_attn(
    const float* __restrict__ Wver, const float* __restrict__ Whor)
{
    __shared__ float sT[3][8][4][128];   // arr, head, line-in-block, pos (48KB)

    int t    = threadIdx.x;
    int wid  = t >> 5;
    int lane = t & 31;
    int bid  = blockIdx.x;               // 512 = 2 dir * 8 sb * 32 groups
    int dir  = bid >> 8;
    int sb   = (bid >> 5) & 7;
    int lg   = bid & 31;
    int c0   = lg * 4;                   // first line of this block

    const float* base_arr[3] = { &g_Q[sb][0][0], &g_K[sb][0][0], &g_V[sb][0][0] };

    // ---- stage into smem ----
    if (dir == 0) {
        int off = (c0 + wid) * 128 + lane * 4;
#pragma unroll
        for (int a = 0; a < 3; ++a)
#pragma unroll
            for (int h = 0; h < 8; ++h) {
                float4 v = *(const float4*)(base_arr[a] + h * PLANE + off);
                *(float4*)&sT[a][h][wid][lane * 4] = v;
            }
    } else {
        int off = t * 128 + c0;
#pragma unroll
        for (int a = 0; a < 3; ++a)
#pragma unroll
            for (int h = 0; h < 8; ++h) {
                float4 v = *(const float4*)(base_arr[a] + h * PLANE + off);
                sT[a][h][0][t] = v.x;
                sT[a][h][1][t] = v.y;
                sT[a][h][2][t] = v.z;
                sT[a][h][3][t] = v.w;
            }
    }
    __syncthreads();

    const float* wdp = dir ? Wver : Whor;

    const float invf[NDEG + 1] = {
        1.0f, 1.0f, 0.5f, 1.0f / 6.0f, 1.0f / 24.0f, 1.0f / 120.0f,
        1.0f / 720.0f, 1.0f / 5040.0f, 1.0f / 40320.0f, 1.0f / 362880.0f,
        1.0f / 3628800.0f, 1.0f / 39916800.0f, 1.0f / 479001600.0f,
        1.0f / 6227020800.0f, 1.0f / 87178291200.0f };

    float fl0 = 0.f, fl1 = 0.f, fl2 = 0.f, fl3 = 0.f;

#pragma unroll 1
    for (int head = 0; head < 8; ++head) {
        float wdh = wdp[head];
        float4 q4 = *(const float4*)&sT[0][head][wid][lane * 4];
        float4 k4 = *(const float4*)&sT[1][head][wid][lane * 4];
        float4 v4 = *(const float4*)&sT[2][head][wid][lane * 4];

        float m[NDEG + 1];
        float mv[NDEG + 1];
#pragma unroll
        for (int n = 0; n <= NDEG; ++n) { m[n] = 0.f; mv[n] = 0.f; }

        {
            float kk, vv, tt;
#define ACCUM(KX, VX)                                        \
            kk = (KX); vv = (VX); tt = kk;                   \
            mv[0] += vv;                                     \
            _Pragma("unroll")                                \
            for (int n = 1; n <= NDEG; ++n) {                \
                m[n] += tt;                                  \
                mv[n] = fmaf(tt, vv, mv[n]);                 \
                tt *= kk;                                    \
            }
            ACCUM(k4.x, v4.x)
            ACCUM(k4.y, v4.y)
            ACCUM(k4.z, v4.z)
            ACCUM(k4.w, v4.w)
#undef ACCUM
        }

#pragma unroll
        for (int off = 16; off; off >>= 1) {
            mv[0] += __shfl_xor_sync(0xffffffffu, mv[0], off);
#pragma unroll
            for (int n = 1; n <= NDEG; ++n) {
                m[n]  += __shfl_xor_sync(0xffffffffu, m[n],  off);
                mv[n] += __shfl_xor_sync(0xffffffffu, mv[n], off);
            }
        }

        m[0] = 128.0f;
#pragma unroll
        for (int n = 2; n <= NDEG; ++n) {
            m[n]  *= invf[n];
            mv[n] *= invf[n];
        }

#define EVAL(QX, FL)                                          \
        {                                                     \
            float q = (QX);                                   \
            float den = m[NDEG], num = mv[NDEG];              \
            _Pragma("unroll")                                 \
            for (int n = NDEG - 1; n >= 0; --n) {             \
                den = fmaf(den, q, m[n]);                     \
                num = fmaf(num, q, mv[n]);                    \
            }                                                 \
            FL = fmaf(wdh, __fdividef(num, den), FL);         \
        }
        EVAL(q4.x, fl0)
        EVAL(q4.y, fl1)
        EVAL(q4.z, fl2)
        EVAL(q4.w, fl3)
#undef EVAL
    }

    int base = (c0 + wid) * 128 + lane * 4;
    *(float4*)&g_flow[dir][sb][base] = make_float4(fl0, fl1, fl2, fl3);
}

// ---------------------------------------------------------------------------
// K3: bilinear border grid-sample. Thread owns BOTH x-parities of an output
// pixel pair (y, 2*w2 / 2*w2+1) for a 4-channel chunk -> dense float2 stores.
// ---------------------------------------------------------------------------
__global__ __launch_bounds__(256) void k_warp(
    const float* __restrict__ ref, float* __restrict__ out)
{
    int idx = blockIdx.x * 256 + threadIdx.x;  // 1048576 = 2*16*256*128
    int w2  = idx & 127;
    int y   = (idx >> 7) & 255;
    int cch = (idx >> 15) & 15;                // 4-channel chunk
    int b   = idx >> 19;
    int dyp = y & 1, h2 = y >> 1;

    // x-parity subs for this row parity: dx=0 -> sA, dx=1 -> sB
    int sA = dyp ? 3 : 0;
    int sB = dyp ? 1 : 2;
    int sbA = sA * 2 + b, sbB = sB * 2 + b;

    // --- sub A (dx = 0) ---
    float fxA = g_flow[0][sbA][(h2 << 7) + w2];
    float fyA = g_flow[1][sbA][(w2 << 7) + h2];
    float ixA = (float)w2 + fxA, iyA = (float)h2 + fyA;
    float xfA = floorf(ixA), yfA = floorf(iyA);
    float wxA = ixA - xfA, wyA = iyA - yfA;
    int x0A = (int)xfA, y0A = (int)yfA;
    int x0cA = min(max(x0A, 0), 127), x1cA = min(max(x0A + 1, 0), 127);
    int y0cA = min(max(y0A, 0), 127), y1cA = min(max(y0A + 1, 0), 127);
    int oA00 = (2 * y0cA + dyp) * 256 + 2 * x0cA;
    int oA01 = (2 * y0cA + dyp) * 256 + 2 * x1cA;
    int oA10 = (2 * y1cA + dyp) * 256 + 2 * x0cA;
    int oA11 = (2 * y1cA + dyp) * 256 + 2 * x1cA;
    float wA11 = wxA * wyA;
    float wA01 = wxA - wA11;
    float wA10 = wyA - wA11;
    float wA00 = 1.f - wxA - wyA + wA11;

    // --- sub B (dx = 1) ---
    float fxB = g_flow[0][sbB][(h2 << 7) + w2];
    float fyB = g_flow[1][sbB][(w2 << 7) + h2];
    float ixB = (float)w2 + fxB, iyB = (float)h2 + fyB;
    float xfB = floorf(ixB), yfB = floorf(iyB);
    float wxB = ixB - xfB, wyB = iyB - yfB;
    int x0B = (int)xfB, y0B = (int)yfB;
    int x0cB = min(max(x0B, 0), 127), x1cB = min(max(x0B + 1, 0), 127);
    int y0cB = min(max(y0B, 0), 127), y1cB = min(max(y0B + 1, 0), 127);
    int oB00 = (2 * y0cB + dyp) * 256 + 2 * x0cB + 1;
    int oB01 = (2 * y0cB + dyp) * 256 + 2 * x1cB + 1;
    int oB10 = (2 * y1cB + dyp) * 256 + 2 * x0cB + 1;
    int oB11 = (2 * y1cB + dyp) * 256 + 2 * x1cB + 1;
    float wB11 = wxB * wyB;
    float wB01 = wxB - wB11;
    float wB10 = wyB - wB11;
    float wB00 = 1.f - wxB - wyB + wB11;

    int c0 = cch * 4;
    const float* rp = ref + ((size_t)b * 64 + c0) * 65536;
    float*       op = out + ((size_t)b * 64 + c0) * 65536 + y * 256 + 2 * w2;

#pragma unroll
    for (int cc = 0; cc < 4; cc += 2) {
        float a00[2], a01[2], a10[2], a11[2];
        float b00[2], b01[2], b10[2], b11[2];
#pragma unroll
        for (int c = 0; c < 2; ++c) {
            const float* p = rp + (size_t)(cc + c) * 65536;
            a00[c] = p[oA00]; a01[c] = p[oA01];
            a10[c] = p[oA10]; a11[c] = p[oA11];
            b00[c] = p[oB00]; b01[c] = p[oB01];
            b10[c] = p[oB10]; b11[c] = p[oB11];
        }
#pragma unroll
        for (int c = 0; c < 2; ++c) {
            float vA = wA00 * a00[c];
            vA = fmaf(wA01, a01[c], vA);
            vA = fmaf(wA10, a10[c], vA);
            vA = fmaf(wA11, a11[c], vA);
            float vB = wB00 * b00[c];
            vB = fmaf(wB01, b01[c], vB);
            vB = fmaf(wB10, b10[c], vB);
            vB = fmaf(wB11, b11[c], vB);
            *(float2*)(op + (size_t)(cc + c) * 65536) = make_float2(vA, vB);
        }
    }
}

// ---------------------------------------------------------------------------
extern "C" void kernel_launch(void* const* d_in, const int* in_sizes, int n_in,
                              void* d_out, int out_size)
{
    const float* cur  = (const float*)d_in[0];
    const float* ref  = (const float*)d_in[1];
    const float* Wq   = (const float*)d_in[2];
    const float* Wk   = (const float*)d_in[3];
    const float* Wv   = (const float*)d_in[4];
    const float* Wver = (const float*)d_in[5];
    const float* Whor = (const float*)d_in[6];
    float* out = (float*)d_out;

    k_qkv<<<512, 256>>>(cur, ref, Wq, Wk, Wv);
    k_attn<<<512, 128>>>(Wver, Whor);
    k_warp<<<4096, 256>>>(ref, out);
}

// round 9
// speedup vs baseline: 1.1042x; 1.1042x over previous
#include <cuda_runtime.h>
#include <cstdint>

// ---------------------------------------------------------------------------
// CrossWarpingModule: B=2, C=64, H=W=256 -> 4 parity sub-images of 128x128,
// 8-head axial attention (per-head channel dim = 1), flow, bilinear warp.
//
//   K1  k_qkv  : 1x1 convs -> Q, K, V. cp.async double-buffered smem staging
//                (register-free loads -> deep MLP -> DRAM-roofline streaming).
//                Each thread copies 64B/tile (4 x 16B cp.async).
//   K2  k_attn : MOMENT-BASED axial softmax (exp(qk) = sum q^n/n! k^n ->
//                29 per-line moments + deg-14 Horner per query), with
//                in-kernel transpose for the vertical direction.
//   K3  k_warp : bilinear border grid-sample + parity re-interleave
//                (4x channel split, 8-channel gather batches).
// ---------------------------------------------------------------------------

#define PLANE 16384  // 128*128
typedef unsigned long long u64;
typedef unsigned int u32;

__device__ float g_Q [8][8][PLANE];
__device__ float g_K [8][8][PLANE];
__device__ float g_V [8][8][PLANE];
__device__ float g_flow[2][8][PLANE];  // dir0 = horizontal, dir1 = vertical

// ------------------------- packed f32x2 helpers ----------------------------
__device__ __forceinline__ u64 pk2f(float lo, float hi) {
    u64 r; asm("mov.b64 %0,{%1,%2};" : "=l"(r) : "f"(lo), "f"(hi)); return r;
}
__device__ __forceinline__ void upk2f(u64 v, float& lo, float& hi) {
    asm("mov.b64 {%0,%1},%2;" : "=f"(lo), "=f"(hi) : "l"(v));
}
__device__ __forceinline__ u64 fma2(u64 a, u64 b, u64 c) {
    u64 d; asm("fma.rn.f32x2 %0,%1,%2,%3;" : "=l"(d) : "l"(a), "l"(b), "l"(c)); return d;
}
__device__ __forceinline__ void cp16(u32 smem_dst, const void* gsrc) {
    asm volatile("cp.async.cg.shared.global [%0], [%1], 16;\n"
                 :: "r"(smem_dst), "l"(gsrc) : "memory");
}
__device__ __forceinline__ void cp_commit() {
    asm volatile("cp.async.commit_group;\n" ::: "memory");
}
template <int N> __device__ __forceinline__ void cp_wait() {
    asm volatile("cp.async.wait_group %0;\n" :: "n"(N) : "memory");
}

// ---------------------------------------------------------------------------
// K1: QKV projections via cp.async-staged tiles.
// Block = one original row (b, y) = 128 pixel-pairs. 8-channel double-buffered
// tiles of cur AND ref staged to smem. Per tile each thread copies 64B
// contiguous (4 x cp.async 16B): thread t -> stream t>>7, channel (t>>4)&7,
// float offset (t&15)*16. 2 streams * 8 ch * 1KB = 16KB per tile.
// Compute: threads t<128 accumulate Q (8 packed accs) for pair p=t from cur;
// threads t>=128 accumulate K and V (16 packed accs) for pair p=t-128 from ref.
// ---------------------------------------------------------------------------
__global__ __launch_bounds__(256) void k_qkv(
    const float* __restrict__ cur, const float* __restrict__ ref,
    const float* __restrict__ Wq, const float* __restrict__ Wk,
    const float* __restrict__ Wv)
{
    __shared__ u64 sW[3][512];               // 12 KB packed weights
    __shared__ float sIn[2][2][8][256];      // [buf][stream][ch][x]  32 KB

    int t = threadIdx.x;
    for (int i = t; i < 512; i += 256) {
        float wq = Wq[i], wk = Wk[i], wv = Wv[i];
        sW[0][i] = pk2f(wq, wq);
        sW[1][i] = pk2f(wk, wk);
        sW[2][i] = pk2f(wv, wv);
    }

    int row = blockIdx.x;                    // 512 rows = 2(b) * 256(y)
    int b   = row >> 8;
    int y   = row & 255;

    // cp.async mapping: stream (cur/ref), channel-in-tile, 64B slice
    int ls = t >> 7;                         // 0 = cur, 1 = ref
    int lc = (t >> 4) & 7;                   // channel within 8-ch tile
    int x0 = (t & 15) * 16;                  // float offset within row
    const float* g0 = (ls ? ref : cur)
        + ((size_t)b * 64 + lc) * 65536 + y * 256 + x0;
    u32 sdst = (u32)__cvta_generic_to_shared(&sIn[0][ls][lc][x0]);
    const u32 BUFSTRIDE = (u32)(2 * 8 * 256 * 4);  // bytes between buffers

    // prefetch tile 0 (4 x 16B per thread)
#pragma unroll
    for (int k = 0; k < 4; ++k)
        cp16(sdst + k * 16, g0 + k * 4);
    cp_commit();

    int half = t >> 7;                       // 0: Q-role, 1: KV-role
    int p    = t & 127;                      // pixel pair
    u64 acc0[8], acc1[8];
#pragma unroll
    for (int h = 0; h < 8; ++h) { acc0[h] = 0ull; acc1[h] = 0ull; }

#pragma unroll
    for (int tile = 0; tile < 8; ++tile) {
        int buf = tile & 1;
        if (tile < 7) {
            u32 d = sdst + (u32)((tile + 1) & 1) * BUFSTRIDE;
            const float* g = g0 + (size_t)(tile + 1) * 8 * 65536;
#pragma unroll
            for (int k = 0; k < 4; ++k)
                cp16(d + k * 16, g + k * 4);
            cp_commit();
            cp_wait<1>();
        } else {
            cp_wait<0>();
        }
        __syncthreads();

        int c0 = tile * 8;
        if (half == 0) {
#pragma unroll
            for (int c = 0; c < 8; ++c) {
                float2 xv = *(const float2*)&sIn[buf][0][c][2 * p];
                u64 x01 = pk2f(xv.x, xv.y);
#pragma unroll
                for (int h = 0; h < 8; ++h)
                    acc0[h] = fma2(sW[0][h * 64 + c0 + c], x01, acc0[h]);
            }
        } else {
#pragma unroll
            for (int c = 0; c < 8; ++c) {
                float2 xv = *(const float2*)&sIn[buf][1][c][2 * p];
                u64 x01 = pk2f(xv.x, xv.y);
#pragma unroll
                for (int h = 0; h < 8; ++h) {
                    acc0[h] = fma2(sW[1][h * 64 + c0 + c], x01, acc0[h]);
                    acc1[h] = fma2(sW[2][h * 64 + c0 + c], x01, acc1[h]);
                }
            }
        }
        __syncthreads();
    }

    // parity sub mapping: (dy,dx) -> s : (0,0)->0 (1,1)->1 (0,1)->2 (1,0)->3
    int dyp = y & 1, h2 = y >> 1;
    int s0  = dyp ? 3 : 0;                   // even-x pixel (lo lane)
    int s1  = dyp ? 1 : 2;                   // odd-x pixel (hi lane)
    int sb0 = s0 * 2 + b, sb1 = s1 * 2 + b;
    int off = h2 * 128 + p;

    if (half == 0) {
#pragma unroll
        for (int h = 0; h < 8; ++h) {
            float lo, hi;
            upk2f(acc0[h], lo, hi);
            g_Q[sb0][h][off] = lo; g_Q[sb1][h][off] = hi;
        }
    } else {
#pragma unroll
        for (int h = 0; h < 8; ++h) {
            float lo, hi;
            upk2f(acc0[h], lo, hi);
            g_K[sb0][h][off] = lo; g_K[sb1][h][off] = hi;
            upk2f(acc1[h], lo, hi);
            g_V[sb0][h][off] = lo; g_V[sb1][h][off] = hi;
        }
    }
}

// ---------------------------------------------------------------------------
// K2: moment-based axial attention with in-kernel transpose for dir=1.
// Block = (dir, sb, 4 lines); 128 threads, warp per line.
// ---------------------------------------------------------------------------
#define NDEG 14

__global__ __launch_bounds__(128) void k_attn(
    const float* __restrict__ Wver, const float* __restrict__ Whor)
{
    __shared__ float sT[3][8][4][128];   // arr, head, line-in-block, pos (48KB)

    int t    = threadIdx.x;
    int wid  = t >> 5;
    int lane = t & 31;
    int bid  = blockIdx.x;               // 512 = 2 dir * 8 sb * 32 groups
    int dir  = bid >> 8;
    int sb   = (bid >> 5) & 7;
    int lg   = bid & 31;
    int c0   = lg * 4;                   // first line of this block

    const float* base_arr[3] = { &g_Q[sb][0][0], &g_K[sb][0][0], &g_V[sb][0][0] };

    if (dir == 0) {
        int off = (c0 + wid) * 128 + lane * 4;
#pragma unroll
        for (int a = 0; a < 3; ++a)
#pragma unroll
            for (int h = 0; h < 8; ++h) {
                float4 v = *(const float4*)(base_arr[a] + h * PLANE + off);
                *(float4*)&sT[a][h][wid][lane * 4] = v;
            }
    } else {
        int off = t * 128 + c0;
#pragma unroll
        for (int a = 0; a < 3; ++a)
#pragma unroll
            for (int h = 0; h < 8; ++h) {
                float4 v = *(const float4*)(base_arr[a] + h * PLANE + off);
                sT[a][h][0][t] = v.x;
                sT[a][h][1][t] = v.y;
                sT[a][h][2][t] = v.z;
                sT[a][h][3][t] = v.w;
            }
    }
    __syncthreads();

    const float* wdp = dir ? Wver : Whor;

    const float invf[NDEG + 1] = {
        1.0f, 1.0f, 0.5f, 1.0f / 6.0f, 1.0f / 24.0f, 1.0f / 120.0f,
        1.0f / 720.0f, 1.0f / 5040.0f, 1.0f / 40320.0f, 1.0f / 362880.0f,
        1.0f / 3628800.0f, 1.0f / 39916800.0f, 1.0f / 479001600.0f,
        1.0f / 6227020800.0f, 1.0f / 87178291200.0f };

    float fl0 = 0.f, fl1 = 0.f, fl2 = 0.f, fl3 = 0.f;

#pragma unroll 1
    for (int head = 0; head < 8; ++head) {
        float wdh = wdp[head];
        float4 q4 = *(const float4*)&sT[0][head][wid][lane * 4];
        float4 k4 = *(const float4*)&sT[1][head][wid][lane * 4];
        float4 v4 = *(const float4*)&sT[2][head][wid][lane * 4];

        float m[NDEG + 1];
        float mv[NDEG + 1];
#pragma unroll
        for (int n = 0; n <= NDEG; ++n) { m[n] = 0.f; mv[n] = 0.f; }

        {
            float kk, vv, tt;
#define ACCUM(KX, VX)                                        \
            kk = (KX); vv = (VX); tt = kk;                   \
            mv[0] += vv;                                     \
            _Pragma("unroll")                                \
            for (int n = 1; n <= NDEG; ++n) {                \
                m[n] += tt;                                  \
                mv[n] = fmaf(tt, vv, mv[n]);                 \
                tt *= kk;                                    \
            }
            ACCUM(k4.x, v4.x)
            ACCUM(k4.y, v4.y)
            ACCUM(k4.z, v4.z)
            ACCUM(k4.w, v4.w)
#undef ACCUM
        }

#pragma unroll
        for (int off = 16; off; off >>= 1) {
            mv[0] += __shfl_xor_sync(0xffffffffu, mv[0], off);
#pragma unroll
            for (int n = 1; n <= NDEG; ++n) {
                m[n]  += __shfl_xor_sync(0xffffffffu, m[n],  off);
                mv[n] += __shfl_xor_sync(0xffffffffu, mv[n], off);
            }
        }

        m[0] = 128.0f;
#pragma unroll
        for (int n = 2; n <= NDEG; ++n) {
            m[n]  *= invf[n];
            mv[n] *= invf[n];
        }

#define EVAL(QX, FL)                                          \
        {                                                     \
            float q = (QX);                                   \
            float den = m[NDEG], num = mv[NDEG];              \
            _Pragma("unroll")                                 \
            for (int n = NDEG - 1; n >= 0; --n) {             \
                den = fmaf(den, q, m[n]);                     \
                num = fmaf(num, q, mv[n]);                    \
            }                                                 \
            FL = fmaf(wdh, __fdividef(num, den), FL);         \
        }
        EVAL(q4.x, fl0)
        EVAL(q4.y, fl1)
        EVAL(q4.z, fl2)
        EVAL(q4.w, fl3)
#undef EVAL
    }

    int base = (c0 + wid) * 128 + lane * 4;
    *(float4*)&g_flow[dir][sb][base] = make_float4(fl0, fl1, fl2, fl3);
}

// ---------------------------------------------------------------------------
// K3: bilinear border grid-sample + parity re-interleave.
// 4x channel-split; gathers batched 8 channels (32 loads in flight).
// ---------------------------------------------------------------------------
__global__ __launch_bounds__(256) void k_warp(
    const float* __restrict__ ref, float* __restrict__ out)
{
    int idx = blockIdx.x * 256 + threadIdx.x;   // 524288
    int pix = idx & 16383;
    int cid = (idx >> 14) & 3;                  // channel chunk 0..3
    int sb  = idx >> 16;                        // 0..7
    int h2  = pix >> 7, w2 = pix & 127;
    int s   = sb >> 1, b = sb & 1;
    int dy  = (s == 1 || s == 3) ? 1 : 0;
    int dx  = (s == 1 || s == 2) ? 1 : 0;

    float fx = g_flow[0][sb][(h2 << 7) + w2];
    float fy = g_flow[1][sb][(w2 << 7) + h2];
    float ix = (float)w2 + fx;
    float iy = (float)h2 + fy;
    float x0f = floorf(ix), y0f = floorf(iy);
    float wx = ix - x0f, wy = iy - y0f;
    int x0 = (int)x0f, y0 = (int)y0f;
    int x0c = min(max(x0, 0), 127), x1c = min(max(x0 + 1, 0), 127);
    int y0c = min(max(y0, 0), 127), y1c = min(max(y0 + 1, 0), 127);

    int X0 = 2 * x0c + dx, X1 = 2 * x1c + dx;
    int Y0 = 2 * y0c + dy, Y1 = 2 * y1c + dy;
    int o00 = Y0 * 256 + X0, o01 = Y0 * 256 + X1;
    int o10 = Y1 * 256 + X0, o11 = Y1 * 256 + X1;

    float w11 = wx * wy;
    float w01 = wx - w11;
    float w10 = wy - w11;
    float w00 = 1.f - wx - wy + w11;

    int c0 = cid * 16;
    const float* rp = ref + ((size_t)b * 64 + c0) * 65536;
    float*       op = out + ((size_t)b * 64 + c0) * 65536
                          + (2 * h2 + dy) * 256 + (2 * w2 + dx);

#pragma unroll
    for (int cc = 0; cc < 16; cc += 8) {
        float t00[8], t01[8], t10[8], t11[8];
#pragma unroll
        for (int c = 0; c < 8; ++c) {
            const float* p = rp + (size_t)(cc + c) * 65536;
            t00[c] = p[o00];
            t01[c] = p[o01];
            t10[c] = p[o10];
            t11[c] = p[o11];
        }
#pragma unroll
        for (int c = 0; c < 8; ++c) {
            float v = w00 * t00[c];
            v = fmaf(w01, t01[c], v);
            v = fmaf(w10, t10[c], v);
            v = fmaf(w11, t11[c], v);
            op[(size_t)(cc + c) * 65536] = v;
        }
    }
}

// ---------------------------------------------------------------------------
extern "C" void kernel_launch(void* const* d_in, const int* in_sizes, int n_in,
                              void* d_out, int out_size)
{
    const float* cur  = (const float*)d_in[0];
    const float* ref  = (const float*)d_in[1];
    const float* Wq   = (const float*)d_in[2];
    const float* Wk   = (const float*)d_in[3];
    const float* Wv   = (const float*)d_in[4];
    const float* Wver = (const float*)d_in[5];
    const float* Whor = (const float*)d_in[6];
    float* out = (float*)d_out;

    k_qkv<<<512, 256>>>(cur, ref, Wq, Wk, Wv);
    k_attn<<<512, 128>>>(Wver, Whor);
    k_warp<<<2048, 256>>>(ref, out);
}